// round 13
// baseline (speedup 1.0000x reference)
#include <cuda_runtime.h>
#include <cuda_bf16.h>

// Problem constants
#define Bsz   4
#define NODES 51
#define MODAL 4
#define SEQ   256
#define DM    128
#define DK    64
#define NBN   (Bsz * NODES)          // 204
#define GRID_N 32                    // table nodes per (bn, j)

// Producer/consumer handshake state (reset by block 0 at end of every run)
__device__ float g_sc4[4];           // {A2, C2, Wm, Bm}
__device__ int   g_flag = 0;         // 1 = scalars published
__device__ int   g_done = 0;         // consumers that have read the scalars

__device__ __forceinline__ float fast_exp2(float x) {
    float y;
    asm("ex2.approx.ftz.f32 %0, %1;" : "=f"(y) : "f"(x));
    return y;
}

// ---- packed f32x2 helpers ----
typedef unsigned long long u64;
__device__ __forceinline__ u64 pk2(float lo, float hi) {
    u64 r;
    asm("mov.b64 %0, {%1, %2};" : "=l"(r) : "f"(lo), "f"(hi));
    return r;
}
__device__ __forceinline__ void upk2(u64 p, float& lo, float& hi) {
    asm("mov.b64 {%0, %1}, %2;" : "=f"(lo), "=f"(hi) : "l"(p));
}
__device__ __forceinline__ u64 mul2(u64 a, u64 b) {
    u64 r;
    asm("mul.rn.f32x2 %0, %1, %2;" : "=l"(r) : "l"(a), "l"(b));
    return r;
}
__device__ __forceinline__ u64 fma2(u64 a, u64 b, u64 c) {
    u64 r;
    asm("fma.rn.f32x2 %0, %1, %2, %3;" : "=l"(r) : "l"(a), "l"(b), "l"(c));
    return r;
}
__device__ __forceinline__ u64 add2(u64 a, u64 b) {
    u64 r;
    asm("add.rn.f32x2 %0, %1, %2;" : "=l"(r) : "l"(a), "l"(b));
    return r;
}

__device__ __forceinline__ int ld_acquire_gpu(const int* p) {
    int v;
    asm volatile("ld.acquire.gpu.s32 %0, [%1];" : "=r"(v) : "l"(p) : "memory");
    return v;
}
__device__ __forceinline__ int ld_relaxed_gpu(const int* p) {
    int v;
    asm volatile("ld.relaxed.gpu.s32 %0, [%1];" : "=r"(v) : "l"(p) : "memory");
    return v;
}

// ---------------------------------------------------------------------------
// ONE kernel. Block = bn (204 x 512 threads, 16 warps).
// Phase A (parallel):
//   warps 0-7 (all blocks): load x tile (float4) + per-warp min/max.
//   warps 8-15, block 0:    weight scalars {A2,C2,Wm,Bm}; publish + release flag.
//   tid 256,  blocks >0:    acquire-poll flag; copy scalars to smem; g_done++.
// Phase B: tabulate f_j on a 32-node grid (warp-uniform j/seg, LDS broadcast).
// Phase C: Catmull-Rom interpolation, 2 outputs/thread.
// Tail:    block 0 waits for all consumers' early g_done bumps, resets state.
// ---------------------------------------------------------------------------
__global__ __launch_bounds__(512, 2) void mmf_one_kernel(
    const float* __restrict__ x,
    const float* __restrict__ Wq, const float* __restrict__ bq,
    const float* __restrict__ Wk,
    const float* __restrict__ Wv, const float* __restrict__ bv,
    float* __restrict__ out) {
    const int bn = blockIdx.x;
    const int tid = threadIdx.x;
    const int wid = tid >> 5;          // 0..15
    const int lane = tid & 31;

    __shared__ float4 sx4[MODAL][SEQ / 4];     // 4 KB x tile
    __shared__ float sF[MODAL][GRID_N];        // 512 B table
    __shared__ float sNum[3][MODAL][GRID_N];   // seg 1..3 partials
    __shared__ float sDen[3][MODAL][GRID_N];
    __shared__ float wmax[8], wmin[8];
    __shared__ float wpart[8][3];              // block-0 scalar partials
    __shared__ float spb;                      // block-0 bv sum
    __shared__ float ssc[4];                   // {A2, C2, Wm, Bm}

    // ======== Phase A ========
    if (tid < 256) {
        // x tile + per-warp min/max (warps 0-7, every block)
        float4 v = ((const float4*)(x + (size_t)bn * (MODAL * SEQ)))[tid];
        ((float4*)sx4)[tid] = v;
        float mx = fmaxf(fmaxf(v.x, v.y), fmaxf(v.z, v.w));
        float mn = fminf(fminf(v.x, v.y), fminf(v.z, v.w));
#pragma unroll
        for (int off = 16; off; off >>= 1) {
            mx = fmaxf(mx, __shfl_xor_sync(0xffffffff, mx, off));
            mn = fminf(mn, __shfl_xor_sync(0xffffffff, mn, off));
        }
        if (lane == 0) { wmax[wid] = mx; wmin[wid] = mn; }
    } else if (bn == 0) {
        // Producer: warps 8-15 compute scalars. Warp ww owns rows 8ww..8ww+7.
        const int ww = wid - 8;
        float pa = 0.f, pc = 0.f, pv = 0.f;
#pragma unroll
        for (int r = 0; r < 8; r++) {
            const int row = ww * 8 + r;
            float4 q  = ((const float4*)(Wq + row * DM))[lane];
            float4 kk = ((const float4*)(Wk + row * DM))[lane];
            float4 vv = ((const float4*)(Wv + row * DM))[lane];
            float sq = (q.x + q.y) + (q.z + q.w);
            float sk = (kk.x + kk.y) + (kk.z + kk.w);
            float sv = (vv.x + vv.y) + (vv.z + vv.w);
#pragma unroll
            for (int off = 16; off; off >>= 1) {
                sq += __shfl_xor_sync(0xffffffff, sq, off);
                sk += __shfl_xor_sync(0xffffffff, sk, off);
                sv += __shfl_xor_sync(0xffffffff, sv, off);
            }
            pa = fmaf(sq, sk, pa);
            pc = fmaf(bq[row], sk, pc);
            pv += sv;
        }
        if (lane == 0) {
            wpart[ww][0] = pa;
            wpart[ww][1] = pc;
            wpart[ww][2] = pv;
        }
        if (ww == 7) {
            float pb = bv[lane] + bv[lane + 32];
#pragma unroll
            for (int off = 16; off; off >>= 1) pb += __shfl_xor_sync(0xffffffff, pb, off);
            if (lane == 0) spb = pb;
        }
        asm volatile("bar.sync 1, 256;" ::: "memory");   // warps 8-15 only
        if (ww == 0) {
            float qa = (lane < 8) ? wpart[lane][0] : 0.f;
            float qc = (lane < 8) ? wpart[lane][1] : 0.f;
            float qv = (lane < 8) ? wpart[lane][2] : 0.f;
#pragma unroll
            for (int off = 4; off; off >>= 1) {
                qa += __shfl_xor_sync(0xffffffff, qa, off);
                qc += __shfl_xor_sync(0xffffffff, qc, off);
                qv += __shfl_xor_sync(0xffffffff, qv, off);
            }
            if (lane == 0) {
                const float K = 0.125f * 1.4426950408889634f;  // log2e/sqrt(64)
                float A2 = qa * K;
                float C2 = qc * K;
                float Wm = qv * (1.0f / DK) * (1.0f / (MODAL - 1));
                float Bm = spb * (1.0f / DK);
                ssc[0] = A2; ssc[1] = C2; ssc[2] = Wm; ssc[3] = Bm;
                g_sc4[0] = A2; g_sc4[1] = C2; g_sc4[2] = Wm; g_sc4[3] = Bm;
                __threadfence();             // release: values before flag
                atomicExch(&g_flag, 1);
            }
        }
    } else if (tid == 256) {
        // Consumer: acquire-poll the flag, pull scalars to smem, bump g_done.
        while (ld_acquire_gpu(&g_flag) == 0) { /* spin (~1us max) */ }
        ssc[0] = g_sc4[0];
        ssc[1] = g_sc4[1];
        ssc[2] = g_sc4[2];
        ssc[3] = g_sc4[3];
        atomicAdd(&g_done, 1);               // early bump (long before exit)
    }
    __syncthreads();

    // Everyone: scalars + grid params in registers (redundant, no extra sync)
    const float A2  = ssc[0];
    const float C2s = ssc[1];
    const float Wm  = ssc[2];
    const float Bm  = ssc[3];
    float tmx = wmax[0], tmn = wmin[0];
#pragma unroll
    for (int k = 1; k < 8; k++) {
        tmx = fmaxf(tmx, wmax[k]);
        tmn = fminf(tmn, wmin[k]);
    }
    const float a_c1 = fmaf(A2, tmn, C2s);
    const float a_c2 = fmaf(A2, tmx, C2s);
    const float alo = fminf(a_c1, a_c2);
    const float ahi = fmaxf(a_c1, a_c2);
    const float h = (ahi - alo) * (1.0f / (GRID_N - 1));
    const float invh = (ahi > alo) ? (float)(GRID_N - 1) / (ahi - alo) : 0.0f;

    // ======== Phase B: tabulate. Warp-uniform (j, seg); g = lane ========
    {
        const int j   = wid >> 2;      // warp-uniform
        const int seg = wid & 3;       // warp-uniform t-quarter
        const int g   = lane;          // 0..31

        const float ag = fmaf(h, (float)g, alo);
        const u64 a22 = pk2(ag, ag);

        u64 num01 = 0ull, num23 = 0ull;
        u64 den01 = 0ull, den23 = 0ull;
        // all 32 lanes read the SAME address each iteration -> LDS broadcast
        const ulonglong2* __restrict__ row =
            ((const ulonglong2*)&sx4[j][0]) + seg * (SEQ / 16);
#pragma unroll 8
        for (int t4 = 0; t4 < SEQ / 16; t4++) {     // 16 iters x 4 elements
            ulonglong2 xt = row[t4];
            u64 p01 = mul2(a22, xt.x);
            u64 p23 = mul2(a22, xt.y);
            float p0, p1, p2, p3;
            upk2(p01, p0, p1);
            upk2(p23, p2, p3);
            float e0 = fast_exp2(p0);
            float e1 = fast_exp2(p1);
            float e2 = fast_exp2(p2);
            float e3 = fast_exp2(p3);
            u64 e01 = pk2(e0, e1);
            u64 e23 = pk2(e2, e3);
            num01 = fma2(xt.x, e01, num01);
            num23 = fma2(xt.y, e23, num23);
            den01 = add2(den01, e01);
            den23 = add2(den23, e23);
        }
        float n0, n1, n2, n3, d0, d1, d2, d3;
        upk2(num01, n0, n1);
        upk2(num23, n2, n3);
        upk2(den01, d0, d1);
        upk2(den23, d2, d3);
        float num = (n0 + n1) + (n2 + n3);
        float den = (d0 + d1) + (d2 + d3);

        if (seg != 0) {
            sNum[seg - 1][j][g] = num;
            sDen[seg - 1][j][g] = den;
        }
        __syncthreads();
        if (seg == 0) {
            num += (sNum[0][j][g] + sNum[1][j][g]) + sNum[2][j][g];
            den += (sDen[0][j][g] + sDen[1][j][g]) + sDen[2][j][g];
            sF[j][g] = __fdividef(num, den);
        }
    }
    __syncthreads();

    // ======== Phase C: interpolate. 2 outputs per thread ========
#pragma unroll
    for (int rep = 0; rep < 2; rep++) {
        const int idx = tid + rep * 512;     // (i, s) = (idx>>8, idx&255)
        const int i = idx >> 8;

        const float xi = ((const float*)sx4)[idx];
        const float a2 = fmaf(A2, xi, C2s);

        float u = (a2 - alo) * invh;
        int i1 = (int)floorf(u);
        i1 = max(0, min(GRID_N - 2, i1));
        float fr = fminf(fmaxf(u - (float)i1, 0.0f), 1.0f);
        const int im  = max(i1 - 1, 0);
        const int ip2 = min(i1 + 2, GRID_N - 1);

        float acc = 0.f;
#pragma unroll
        for (int j = 0; j < MODAL; j++) {
            if (j == i) continue;
            float p0 = sF[j][im];
            float p1 = sF[j][i1];
            float p2 = sF[j][i1 + 1];
            float p3 = sF[j][ip2];
            // Catmull-Rom
            float c3 = 3.0f * (p1 - p2) + (p3 - p0);
            float c2 = 2.0f * p0 - 5.0f * p1 + 4.0f * p2 - p3;
            float c1 = p2 - p0;
            float f = fmaf(0.5f * fr, fmaf(fr, fmaf(fr, c3, c2), c1), p1);
            acc += f;
        }

        out[(size_t)bn * (MODAL * SEQ) + idx] = fmaf(Wm, acc, Bm);
    }

    // ======== Tail: block 0 resets handshake state for the next replay ======
    if (bn == 0 && tid == 0) {
        // consumers bump g_done right after their poll (early in the kernel),
        // so this wait is essentially free by the time we get here.
        while (ld_relaxed_gpu(&g_done) != NBN - 1) { /* spin */ }
        g_done = 0;
        asm volatile("st.relaxed.gpu.s32 [%0], %1;" :: "l"(&g_flag), "r"(0) : "memory");
    }
}

// ---------------------------------------------------------------------------
// Launch: ONE kernel.
// ---------------------------------------------------------------------------
extern "C" void kernel_launch(void* const* d_in, const int* in_sizes, int n_in,
                              void* d_out, int out_size) {
    const float* x  = (const float*)d_in[0];
    const float* Wq = (const float*)d_in[1];
    const float* bq = (const float*)d_in[2];
    const float* Wk = (const float*)d_in[3];
    const float* Wv = (const float*)d_in[5];
    const float* bv = (const float*)d_in[6];
    float* out = (float*)d_out;

    mmf_one_kernel<<<NBN, 512>>>(x, Wq, bq, Wk, Wv, bv, out);
}

// round 14
// speedup vs baseline: 1.0239x; 1.0239x over previous
#include <cuda_runtime.h>
#include <cuda_bf16.h>

// Problem constants
#define Bsz   4
#define NODES 51
#define MODAL 4
#define SEQ   256
#define DM    128
#define DK    64
#define NBN   (Bsz * NODES)          // 204
#define GRID_N 32                    // table nodes per (bn, j)

// {A2, C2, Wm, Bm} published by the scalars kernel
__device__ float4 g_scv;
// Published tables: [bn][j][node] (~104 KB, L2-resident)
__device__ float g_T[NBN * MODAL * GRID_N];
// Per-bn rendezvous counters (each user resets its own -> replay-safe)
__device__ int g_cnt[NBN];

__device__ __forceinline__ float fast_exp2(float x) {
    float y;
    asm("ex2.approx.ftz.f32 %0, %1;" : "=f"(y) : "f"(x));
    return y;
}

// ---- packed f32x2 helpers ----
typedef unsigned long long u64;
__device__ __forceinline__ u64 pk2(float lo, float hi) {
    u64 r;
    asm("mov.b64 %0, {%1, %2};" : "=l"(r) : "f"(lo), "f"(hi));
    return r;
}
__device__ __forceinline__ void upk2(u64 p, float& lo, float& hi) {
    asm("mov.b64 {%0, %1}, %2;" : "=f"(lo), "=f"(hi) : "l"(p));
}
__device__ __forceinline__ u64 mul2(u64 a, u64 b) {
    u64 r;
    asm("mul.rn.f32x2 %0, %1, %2;" : "=l"(r) : "l"(a), "l"(b));
    return r;
}
__device__ __forceinline__ u64 fma2(u64 a, u64 b, u64 c) {
    u64 r;
    asm("fma.rn.f32x2 %0, %1, %2, %3;" : "=l"(r) : "l"(a), "l"(b), "l"(c));
    return r;
}
__device__ __forceinline__ u64 add2(u64 a, u64 b) {
    u64 r;
    asm("add.rn.f32x2 %0, %1, %2;" : "=l"(r) : "l"(a), "l"(b));
    return r;
}

// ---------------------------------------------------------------------------
// Kernel 1: scalars. ONE block, 512 threads (16 warps); warp w owns rows
// 4w..4w+3 of Wq/Wk/Wv. Publishes {A2, C2, Wm, Bm} as one float4.
// ---------------------------------------------------------------------------
__global__ __launch_bounds__(512) void mmf_scalars_kernel(
    const float* __restrict__ Wq, const float* __restrict__ bq,
    const float* __restrict__ Wk,
    const float* __restrict__ Wv, const float* __restrict__ bv) {
    const int tid = threadIdx.x;
    const int wid = tid >> 5;
    const int lane = tid & 31;

    __shared__ float wpart[16][3];
    __shared__ float spb;

    float pa = 0.f, pc = 0.f, pv = 0.f;
#pragma unroll
    for (int r = 0; r < 4; r++) {
        const int row = wid * 4 + r;
        float4 q  = ((const float4*)(Wq + row * DM))[lane];
        float4 kk = ((const float4*)(Wk + row * DM))[lane];
        float4 vv = ((const float4*)(Wv + row * DM))[lane];
        float sq = (q.x + q.y) + (q.z + q.w);
        float sk = (kk.x + kk.y) + (kk.z + kk.w);
        float sv = (vv.x + vv.y) + (vv.z + vv.w);
#pragma unroll
        for (int off = 16; off; off >>= 1) {
            sq += __shfl_xor_sync(0xffffffff, sq, off);
            sk += __shfl_xor_sync(0xffffffff, sk, off);
            sv += __shfl_xor_sync(0xffffffff, sv, off);
        }
        pa = fmaf(sq, sk, pa);
        pc = fmaf(bq[row], sk, pc);
        pv += sv;
    }
    if (lane == 0) {
        wpart[wid][0] = pa;
        wpart[wid][1] = pc;
        wpart[wid][2] = pv;
    }
    if (wid == 15) {
        float pb = bv[lane] + bv[lane + 32];
#pragma unroll
        for (int off = 16; off; off >>= 1) pb += __shfl_xor_sync(0xffffffff, pb, off);
        if (lane == 0) spb = pb;
    }
    __syncthreads();

    if (wid == 0) {
        float qa = (lane < 16) ? wpart[lane][0] : 0.f;
        float qc = (lane < 16) ? wpart[lane][1] : 0.f;
        float qv = (lane < 16) ? wpart[lane][2] : 0.f;
#pragma unroll
        for (int off = 8; off; off >>= 1) {
            qa += __shfl_xor_sync(0xffffffff, qa, off);
            qc += __shfl_xor_sync(0xffffffff, qc, off);
            qv += __shfl_xor_sync(0xffffffff, qv, off);
        }
        if (lane == 0) {
            const float K = 0.125f * 1.4426950408889634f;  // log2e/sqrt(64)
            float4 s;
            s.x = qa * K;                                   // A2
            s.y = qc * K;                                   // C2
            s.z = qv * (1.0f / DK) * (1.0f / (MODAL - 1));  // Wm
            s.w = spb * (1.0f / DK);                        // Bm
            g_scv = s;
        }
    }
}

// ---------------------------------------------------------------------------
// Kernel 2: main. Block = (bn, jpair): 408 blocks x 256 threads (8 warps).
// Worst SM now carries 1.5 bn of table work (vs 2.0 with 204 blocks).
//  - tile load (256 x float4) + per-warp min/max; g_scv prefetched at entry.
//  - tabulate 2 j's x 32 nodes: warp-uniform (jloc, seg), g = lane,
//    pure LDS broadcast, 64 exps/thread; seg partials combined via smem.
//  - publish own 2 tables to g_T; rendezvous on g_cnt[bn]: SECOND arrival
//    pulls sibling's tables from L2, resets the counter, interps all 1024
//    outputs of this bn. First arrival exits (no waiting).
// ---------------------------------------------------------------------------
__global__ __launch_bounds__(256, 4) void mmf_main_kernel(
    const float* __restrict__ x, float* __restrict__ out) {
    const int blk = blockIdx.x;          // bn*2 + jpair
    const int jp  = blk & 1;
    const int bn  = blk >> 1;
    const int tid = threadIdx.x;
    const int wid = tid >> 5;            // 0..7
    const int lane = tid & 31;

    __shared__ float4 sx4[MODAL][SEQ / 4];   // 4 KB x tile
    __shared__ float sF[MODAL][GRID_N];      // all 4 tables (own 2 + sibling 2)
    __shared__ float sNum[3][2][GRID_N];     // seg 1..3 partials for 2 local j
    __shared__ float sDen[3][2][GRID_N];
    __shared__ float wmax[8], wmin[8];
    __shared__ int sOld;

    // Prefetch scalars (one LDG.128 from L2; written by the previous kernel)
    const float4 sc = __ldg(&g_scv);
    const float A2 = sc.x, C2s = sc.y, Wm = sc.z, Bm = sc.w;

    // ---- Phase 1: x tile + per-warp min/max ----
    float4 v = ((const float4*)(x + (size_t)bn * (MODAL * SEQ)))[tid];
    ((float4*)sx4)[tid] = v;
    {
        float mx = fmaxf(fmaxf(v.x, v.y), fmaxf(v.z, v.w));
        float mn = fminf(fminf(v.x, v.y), fminf(v.z, v.w));
#pragma unroll
        for (int off = 16; off; off >>= 1) {
            mx = fmaxf(mx, __shfl_xor_sync(0xffffffff, mx, off));
            mn = fminf(mn, __shfl_xor_sync(0xffffffff, mn, off));
        }
        if (lane == 0) { wmax[wid] = mx; wmin[wid] = mn; }
    }
    __syncthreads();

    // every thread reduces the 8 warp partials itself (no extra barrier)
    float tmx = wmax[0], tmn = wmin[0];
#pragma unroll
    for (int k = 1; k < 8; k++) {
        tmx = fmaxf(tmx, wmax[k]);
        tmn = fminf(tmn, wmin[k]);
    }
    const float a_c1 = fmaf(A2, tmn, C2s);
    const float a_c2 = fmaf(A2, tmx, C2s);
    const float alo = fminf(a_c1, a_c2);
    const float ahi = fmaxf(a_c1, a_c2);
    const float h = (ahi - alo) * (1.0f / (GRID_N - 1));
    const float invh = (ahi > alo) ? (float)(GRID_N - 1) / (ahi - alo) : 0.0f;

    // ---- Phase 2: tabulate this block's 2 tables ----
    {
        const int jloc = wid >> 2;            // 0/1, warp-uniform
        const int j    = jp * 2 + jloc;       // global modality
        const int seg  = wid & 3;             // warp-uniform t-quarter
        const int g    = lane;                // 0..31

        const float ag = fmaf(h, (float)g, alo);
        const u64 a22 = pk2(ag, ag);

        u64 num01 = 0ull, num23 = 0ull;
        u64 den01 = 0ull, den23 = 0ull;
        // all 32 lanes read the SAME address each iteration -> LDS broadcast
        const ulonglong2* __restrict__ row =
            ((const ulonglong2*)&sx4[j][0]) + seg * (SEQ / 16);
#pragma unroll 8
        for (int t4 = 0; t4 < SEQ / 16; t4++) {     // 16 iters x 4 elements
            ulonglong2 xt = row[t4];
            u64 p01 = mul2(a22, xt.x);
            u64 p23 = mul2(a22, xt.y);
            float p0, p1, p2, p3;
            upk2(p01, p0, p1);
            upk2(p23, p2, p3);
            float e0 = fast_exp2(p0);
            float e1 = fast_exp2(p1);
            float e2 = fast_exp2(p2);
            float e3 = fast_exp2(p3);
            u64 e01 = pk2(e0, e1);
            u64 e23 = pk2(e2, e3);
            num01 = fma2(xt.x, e01, num01);
            num23 = fma2(xt.y, e23, num23);
            den01 = add2(den01, e01);
            den23 = add2(den23, e23);
        }
        float n0, n1, n2, n3, d0, d1, d2, d3;
        upk2(num01, n0, n1);
        upk2(num23, n2, n3);
        upk2(den01, d0, d1);
        upk2(den23, d2, d3);
        float num = (n0 + n1) + (n2 + n3);
        float den = (d0 + d1) + (d2 + d3);

        if (seg != 0) {
            sNum[seg - 1][jloc][g] = num;
            sDen[seg - 1][jloc][g] = den;
        }
        __syncthreads();
        if (seg == 0) {
            num += (sNum[0][jloc][g] + sNum[1][jloc][g]) + sNum[2][jloc][g];
            den += (sDen[0][jloc][g] + sDen[1][jloc][g]) + sDen[2][jloc][g];
            float f = __fdividef(num, den);
            sF[j][g] = f;
            g_T[((size_t)bn * MODAL + j) * GRID_N + g] = f;   // publish
            __threadfence();    // writer's release: STG visible before atomic
        }
    }
    __syncthreads();

    // ---- Rendezvous: second arrival interps the whole bn ----
    if (tid == 0) sOld = atomicAdd(&g_cnt[bn], 1);
    __syncthreads();
    if (sOld == 0) return;     // first arrival: done (sibling will interp)

    // Pull sibling's 2 tables from L2 (bypass L1 via __ldcg)
    {
        const int sibbase = (1 - jp) * 2;
        if (tid < 2 * GRID_N) {
            const int jj = sibbase + (tid >> 5);
            const int gg = tid & 31;
            sF[jj][gg] = __ldcg(&g_T[((size_t)bn * MODAL + jj) * GRID_N + gg]);
        }
        if (tid == 0) g_cnt[bn] = 0;   // reset for next graph replay
    }
    __syncthreads();

    // ---- Phase 3: interpolate. 4 outputs per thread (i = rep, s = tid) ----
#pragma unroll
    for (int i = 0; i < MODAL; i++) {
        const float xi = ((const float*)sx4)[i * SEQ + tid];
        const float a2 = fmaf(A2, xi, C2s);

        float u = (a2 - alo) * invh;
        int i1 = (int)floorf(u);
        i1 = max(0, min(GRID_N - 2, i1));
        float fr = fminf(fmaxf(u - (float)i1, 0.0f), 1.0f);
        const int im  = max(i1 - 1, 0);
        const int ip2 = min(i1 + 2, GRID_N - 1);

        float acc = 0.f;
#pragma unroll
        for (int j = 0; j < MODAL; j++) {
            if (j == i) continue;
            float p0 = sF[j][im];
            float p1 = sF[j][i1];
            float p2 = sF[j][i1 + 1];
            float p3 = sF[j][ip2];
            // Catmull-Rom
            float c3 = 3.0f * (p1 - p2) + (p3 - p0);
            float c2 = 2.0f * p0 - 5.0f * p1 + 4.0f * p2 - p3;
            float c1 = p2 - p0;
            float f = fmaf(0.5f * fr, fmaf(fr, fmaf(fr, c3, c2), c1), p1);
            acc += f;
        }

        out[(size_t)bn * (MODAL * SEQ) + i * SEQ + tid] = fmaf(Wm, acc, Bm);
    }
}

// ---------------------------------------------------------------------------
// Launch
// ---------------------------------------------------------------------------
extern "C" void kernel_launch(void* const* d_in, const int* in_sizes, int n_in,
                              void* d_out, int out_size) {
    const float* x  = (const float*)d_in[0];
    const float* Wq = (const float*)d_in[1];
    const float* bq = (const float*)d_in[2];
    const float* Wk = (const float*)d_in[3];
    const float* Wv = (const float*)d_in[5];
    const float* bv = (const float*)d_in[6];
    float* out = (float*)d_out;

    mmf_scalars_kernel<<<1, 512>>>(Wq, bq, Wk, Wv, bv);
    mmf_main_kernel<<<NBN * 2, 256>>>(x, out);
}